// round 16
// baseline (speedup 1.0000x reference)
#include <cuda_runtime.h>
#include <cstdint>

// HadamardTransform: y[b,:,h,w] = (H_1024 @ pad(x[b,:,h,w]))[0:768] / 32
// FWHT-1024 per pixel, 4 pixels per thread (u128 = 2x packed f32x2),
// TILE=32 pixels / 256 threads / 2 CTAs per SM.
// Pass 1 (c_hi): stage-parallel zero-eliminated FWHT32 (24 live u128),
//                all 24 LDG.128 batched first for max in-flight bytes.
// Pass 2 (c_lo): stage m=16 folded into smem reads; two FWHT16 halves.

#define DIMC          768
#define TILE          32
#define THREADS       256
#define PIX_PER_IMG   3136
#define TILES_PER_IMG 98          // 3136/32

// ---- packed f32x2 ops (sm_103a) ----
__device__ __forceinline__ uint64_t addx2(uint64_t a, uint64_t b) {
    uint64_t d; asm("add.rn.f32x2 %0, %1, %2;" : "=l"(d) : "l"(a), "l"(b)); return d;
}
__device__ __forceinline__ uint64_t subx2(uint64_t a, uint64_t b) {
    const uint64_t NEG1 = 0xBF800000BF800000ULL;
    uint64_t d; asm("fma.rn.f32x2 %0, %1, %2, %3;" : "=l"(d) : "l"(b), "l"(NEG1), "l"(a)); return d;
}
__device__ __forceinline__ uint64_t mulx2(uint64_t a, uint64_t b) {
    uint64_t d; asm("mul.rn.f32x2 %0, %1, %2;" : "=l"(d) : "l"(a), "l"(b)); return d;
}

// 4-pixel value: two packed f32x2 halves (16 bytes)
struct __align__(16) V4 { uint64_t lo, hi; };
__device__ __forceinline__ V4 addV(V4 a, V4 b) { return { addx2(a.lo, b.lo), addx2(a.hi, b.hi) }; }
__device__ __forceinline__ V4 subV(V4 a, V4 b) { return { subx2(a.lo, b.lo), subx2(a.hi, b.hi) }; }
__device__ __forceinline__ V4 mulV(V4 a, uint64_t s) { return { mulx2(a.lo, s), mulx2(a.hi, s) }; }

__device__ __forceinline__ V4 ld4(const float* p) {
    const float4 f = *(const float4*)p;
    V4 v;
    asm("mov.b64 %0, {%1, %2};" : "=l"(v.lo) : "f"(f.x), "f"(f.y));
    asm("mov.b64 %0, {%1, %2};" : "=l"(v.hi) : "f"(f.z), "f"(f.w));
    return v;
}
__device__ __forceinline__ void st4(float* p, V4 v) {
    float a, b, c, d;
    asm("mov.b64 {%0, %1}, %2;" : "=f"(a), "=f"(b) : "l"(v.lo));
    asm("mov.b64 {%0, %1}, %2;" : "=f"(c), "=f"(d) : "l"(v.hi));
    *(float4*)p = make_float4(a, b, c, d);
}

// smem (u128 units): row r (0..767) at (r + (r>>5))*8 + p4.
// 8-lane access phases are 8 contiguous u128 = 128B = all 32 banks once.

__global__ __launch_bounds__(THREADS, 2)
void fwht1024_kernel(const float* __restrict__ x, float* __restrict__ y) {
    extern __shared__ V4 s[];   // 792*8 = 6336 V4 = 101376 B

    const int tid = threadIdx.x;
    const int T   = blockIdx.x;
    const int b   = T / TILES_PER_IMG;
    const int p0  = (T % TILES_PER_IMG) * TILE;

    const int p4 = tid & 7;        // pixel quad -> pixels 4*p4 .. 4*p4+3
    const int g  = tid >> 3;       // 0..31

    const size_t base = (size_t)b * DIMC * PIX_PER_IMG + p0 + 4 * p4;

    // ---- Pass 1: zero-eliminated FWHT32 over channel bits 5..9 ----
    {
        V4 w[24];
        // ALL loads first: 24 independent LDG.128 -> max bytes in flight
        #pragma unroll
        for (int j = 0; j < 24; j++)
            w[j] = ld4(x + base + (size_t)(j * 32 + g) * PIX_PER_IMG);

        // stages m = 1, 2, 4 (within each aligned 8-block; zero block absent)
        #pragma unroll
        for (int st = 0; st < 3; st++) {
            const int m = 1 << st;
            #pragma unroll
            for (int j = 0; j < 24; j++) {
                if (!(j & m)) {
                    V4 a = w[j], c2 = w[j + m];
                    w[j]     = addV(a, c2);
                    w[j + m] = subV(a, c2);
                }
            }
        }
        // stage m = 8: only block pair (0,1); block 2 pairs zeros (no-op)
        #pragma unroll
        for (int j = 0; j < 8; j++) {
            V4 a = w[j], c2 = w[j + 8];
            w[j]     = addV(a, c2);
            w[j + 8] = subV(a, c2);
        }
        // stage m = 16: j=8..15 pair with alias (w[j+16]==w[j+8], minus-half
        // discarded); then j=0..7 standard pairs.
        #pragma unroll
        for (int j = 8; j < 16; j++)
            w[j] = addV(w[j], w[j + 8]);
        #pragma unroll
        for (int j = 0; j < 8; j++) {
            V4 a = w[j], c2 = w[j + 16];
            w[j]      = addV(a, c2);
            w[j + 16] = subV(a, c2);
        }

        #pragma unroll
        for (int j = 0; j < 24; j++)
            s[(j * 33 + g) * 8 + p4] = w[j];
    }
    __syncthreads();

    // ---- Pass 2: stage m=16 folded into reads, two FWHT16 halves ----
    if (g < 24) {
        const uint64_t SCALE = 0x3D0000003D000000ULL;   // (1/32, 1/32)
        const V4* sr = s + (size_t)g * 33 * 8 + p4;

        #pragma unroll
        for (int half = 0; half < 2; half++) {
            V4 u[16];
            if (half == 0) {
                #pragma unroll
                for (int j = 0; j < 16; j++)
                    u[j] = addV(sr[(size_t)j * 8], sr[(size_t)(j + 16) * 8]);
            } else {
                #pragma unroll
                for (int j = 0; j < 16; j++)
                    u[j] = subV(sr[(size_t)j * 8], sr[(size_t)(j + 16) * 8]);
            }

            #pragma unroll
            for (int st = 0; st < 4; st++) {
                const int m = 1 << st;
                #pragma unroll
                for (int j = 0; j < 16; j++) {
                    if (!(j & m)) {
                        V4 a = u[j], c2 = u[j + m];
                        u[j]     = addV(a, c2);
                        u[j + m] = subV(a, c2);
                    }
                }
            }

            #pragma unroll
            for (int k = 0; k < 16; k++)
                st4(y + base + (size_t)(g * 32 + half * 16 + k) * PIX_PER_IMG,
                    mulV(u[k], SCALE));
        }
    }
}

extern "C" void kernel_launch(void* const* d_in, const int* in_sizes, int n_in,
                              void* d_out, int out_size) {
    (void)in_sizes; (void)n_in; (void)out_size;
    const float* x = (const float*)d_in[0];
    float* y = (float*)d_out;

    const int smem_bytes = 792 * 8 * sizeof(V4);   // 101376
    cudaFuncSetAttribute(fwht1024_kernel,
                         cudaFuncAttributeMaxDynamicSharedMemorySize, smem_bytes);

    const int grid = 16 * TILES_PER_IMG;   // 1568 tiles
    fwht1024_kernel<<<grid, THREADS, smem_bytes>>>(x, y);
}

// round 17
// speedup vs baseline: 1.5965x; 1.5965x over previous
#include <cuda_runtime.h>
#include <cstdint>

// HadamardTransform: y[b,:,h,w] = (H_1024 @ pad(x[b,:,h,w]))[0:768] / 32
// FWHT-1024 per pixel, two register passes over channel bits (5-9 then 0-4),
// packed f32x2 math (2 pixels per thread), 64-bit gmem/smem ops throughout.
// Final converged configuration: TILE=16, 256 threads, 3 CTAs/SM, monolithic
// FWHT32 passes, 24 batched LDG.64 (full MLP) with L2::256B prefetch hint,
// direct gmem I/O in both passes, one barrier total.

#define DIMC          768
#define TILE          16          // pixels per CTA
#define THREADS       256
#define PIX_PER_IMG   3136        // 56*56
#define TILES_PER_IMG 196         // 3136/16

// ---- packed f32x2 ops (sm_103a) ----
__device__ __forceinline__ uint64_t addx2(uint64_t a, uint64_t b) {
    uint64_t d; asm("add.rn.f32x2 %0, %1, %2;" : "=l"(d) : "l"(a), "l"(b)); return d;
}
__device__ __forceinline__ uint64_t subx2(uint64_t a, uint64_t b) {
    const uint64_t NEG1 = 0xBF800000BF800000ULL;   // (-1.0f, -1.0f)
    uint64_t d; asm("fma.rn.f32x2 %0, %1, %2, %3;" : "=l"(d) : "l"(b), "l"(NEG1), "l"(a)); return d;
}
__device__ __forceinline__ uint64_t mulx2(uint64_t a, uint64_t b) {
    uint64_t d; asm("mul.rn.f32x2 %0, %1, %2;" : "=l"(d) : "l"(a), "l"(b)); return d;
}

// 64-bit non-coherent load with 256B L2 prefetch (pulls the neighbor tile's
// sectors of the same channel row into L2).
__device__ __forceinline__ uint64_t ldg64_pf256(const float* p) {
    uint64_t d;
    asm("ld.global.nc.L2::256B.b64 %0, [%1];" : "=l"(d) : "l"(p));
    return d;
}

// smem layout (float2 units): row r (0..767) at (r + (r>>5))*8 + p2.
// The per-32-row pad makes both passes' 16-lane LDS/STS.64 phases
// conflict-free (32-row stride = 528 words == 16 mod 32).

__global__ __launch_bounds__(THREADS, 3)
void fwht1024_kernel(const float* __restrict__ x, float* __restrict__ y) {
    extern __shared__ uint64_t s[];   // 792*8 = 6336 u64 = 50688 B

    const int tid = threadIdx.x;
    const int T   = blockIdx.x;
    const int b   = T / TILES_PER_IMG;
    const int p0  = (T % TILES_PER_IMG) * TILE;

    const int p2 = tid & 7;        // pixel pair -> pixels 2*p2, 2*p2+1
    const int g  = tid >> 3;       // 0..31

    const size_t base = (size_t)b * DIMC * PIX_PER_IMG + p0 + 2 * p2;

    // ---- Pass 1: butterfly over channel bits 5..9, gmem -> smem ----
    // Thread owns channels c = j*32 + g; j >= 24 are zero padding.
    {
        uint64_t w[32];
        #pragma unroll
        for (int j = 0; j < 24; j++)
            w[j] = ldg64_pf256(x + base + (size_t)(j * 32 + g) * PIX_PER_IMG);
        #pragma unroll
        for (int j = 24; j < 32; j++)
            w[j] = 0ULL;

        #pragma unroll
        for (int st = 0; st < 5; st++) {
            const int m = 1 << st;
            #pragma unroll
            for (int j = 0; j < 32; j++) {
                if (!(j & m)) {
                    uint64_t a = w[j], c2 = w[j + m];
                    w[j]     = addx2(a, c2);
                    w[j + m] = subx2(a, c2);
                }
            }
        }

        // only intermediates with j < 24 are ever read (outputs keep k < 768)
        #pragma unroll
        for (int j = 0; j < 24; j++)
            s[(j * 33 + g) * 8 + p2] = w[j];
    }
    __syncthreads();

    // ---- Pass 2: butterfly over channel bits 0..4, smem -> gmem ----
    if (g < 24) {
        uint64_t w[32];
        #pragma unroll
        for (int j = 0; j < 32; j++)
            w[j] = s[(g * 33 + j) * 8 + p2];

        #pragma unroll
        for (int st = 0; st < 5; st++) {
            const int m = 1 << st;
            #pragma unroll
            for (int j = 0; j < 32; j++) {
                if (!(j & m)) {
                    uint64_t a = w[j], c2 = w[j + m];
                    w[j]     = addx2(a, c2);
                    w[j + m] = subx2(a, c2);
                }
            }
        }

        const uint64_t SCALE = 0x3D0000003D000000ULL;   // (1/32, 1/32)
        #pragma unroll
        for (int j = 0; j < 32; j++) {
            uint64_t r = mulx2(w[j], SCALE);
            float lo, hi;
            asm("mov.b64 {%0, %1}, %2;" : "=f"(lo), "=f"(hi) : "l"(r));
            *(float2*)(y + base + (size_t)(g * 32 + j) * PIX_PER_IMG)
                = make_float2(lo, hi);
        }
    }
}

extern "C" void kernel_launch(void* const* d_in, const int* in_sizes, int n_in,
                              void* d_out, int out_size) {
    (void)in_sizes; (void)n_in; (void)out_size;
    const float* x = (const float*)d_in[0];
    float* y = (float*)d_out;

    const int smem_bytes = 792 * 8 * sizeof(uint64_t);   // 50688
    cudaFuncSetAttribute(fwht1024_kernel,
                         cudaFuncAttributeMaxDynamicSharedMemorySize, smem_bytes);

    const int grid = 16 * TILES_PER_IMG;   // 3136 tiles
    fwht1024_kernel<<<grid, THREADS, smem_bytes>>>(x, y);
}